// round 2
// baseline (speedup 1.0000x reference)
#include <cuda_runtime.h>
#include <math.h>

// ---------------- problem constants ----------------
#define BB 32
#define CC 192
#define HH 56
#define WW 56
#define HWP 3136            // 56*56
#define HEADS 6
#define DH 32               // head dim
#define WSZ 7
#define NWH 8               // windows per side
#define NWIN 2048           // 32*8*8
#define NTOK 49
#define NROWS 100352        // 2048*49 == 32*3136
#define HID 768
#define EPS_LN 1e-5f

// ---------------- scratch (static device globals; no runtime allocation) -----
__device__ __align__(128) float g_xw  [100352 * 192];  // LN1+window output; reused for proj output
__device__ __align__(128) float g_qkv [100352 * 576];
__device__ __align__(128) float g_attn[100352 * 192];
__device__ __align__(128) float g_x1  [19267584];      // x + attn branch
__device__ __align__(128) float g_ln2 [19267584];
__device__ __align__(128) float g_hid [32 * 768 * 3136];

// ---------------- LN1 + roll(-3,-3) + window partition -----------------------
__global__ __launch_bounds__(256)
void ln1_roll_window(const float* __restrict__ x, const float* __restrict__ g,
                     const float* __restrict__ bt, float* __restrict__ xw) {
    int idx = blockIdx.x * 256 + threadIdx.x;       // rolled-coord pixel id
    if (idx >= NROWS) return;
    int bb = idx / HWP;
    int hw = idx - bb * HWP;
    int h1 = hw / WW;
    int w1 = hw - h1 * WW;
    int hs = h1 + 3; if (hs >= HH) hs -= HH;        // source of roll(-3)
    int ws = w1 + 3; if (ws >= WW) ws -= WW;
    const float* xp = x + (size_t)bb * CC * HWP + hs * WW + ws;
    float s = 0.f, ss = 0.f;
    #pragma unroll 4
    for (int c = 0; c < CC; c++) { float v = xp[(size_t)c * HWP]; s += v; ss += v * v; }
    float mean = s * (1.f / CC);
    float var  = ss * (1.f / CC) - mean * mean;
    float rstd = rsqrtf(var + EPS_LN);
    int win = bb * 64 + (h1 / WSZ) * NWH + (w1 / WSZ);
    int t   = (h1 % WSZ) * WSZ + (w1 % WSZ);
    float* op = xw + ((size_t)win * NTOK + t) * CC;
    #pragma unroll 4
    for (int c = 0; c < CC; c++)
        op[c] = (xp[(size_t)c * HWP] - mean) * rstd * g[c] + bt[c];
}

// ---------------- LN2 (NCHW -> NCHW) -----------------------------------------
__global__ __launch_bounds__(256)
void ln2_kernel(const float* __restrict__ x, const float* __restrict__ g,
                const float* __restrict__ bt, float* __restrict__ out) {
    int idx = blockIdx.x * 256 + threadIdx.x;       // pixel id (b*3136+hw)
    if (idx >= NROWS) return;
    int bb = idx / HWP;
    int hw = idx - bb * HWP;
    const float* xp = x + (size_t)bb * CC * HWP + hw;
    float s = 0.f, ss = 0.f;
    #pragma unroll 4
    for (int c = 0; c < CC; c++) { float v = xp[(size_t)c * HWP]; s += v; ss += v * v; }
    float mean = s * (1.f / CC);
    float var  = ss * (1.f / CC) - mean * mean;
    float rstd = rsqrtf(var + EPS_LN);
    float* op = out + (size_t)bb * CC * HWP + hw;
    #pragma unroll 4
    for (int c = 0; c < CC; c++)
        op[(size_t)c * HWP] = (xp[(size_t)c * HWP] - mean) * rstd * g[c] + bt[c];
}

// ---------------- NT SGEMM: C[M,N] = X[M,K] * Wt[N,K]^T + bias ---------------
// Tiles: M=128, N=64, K=16. 256 threads, 4(n) x 8(m) micro-tile.
__global__ __launch_bounds__(256)
void gemm_nt(const float* __restrict__ X, const float* __restrict__ Wt,
             const float* __restrict__ bias, float* __restrict__ C_,
             int M, int N, int K) {
    __shared__ float Ws[16][68];
    __shared__ float Xs[16][132];
    int m0 = blockIdx.x * 128;
    int n0 = blockIdx.y * 64;
    int tid = threadIdx.x;
    int tx = tid & 15;   // n group of 4
    int ty = tid >> 4;   // m group of 8
    float acc[4][8];
    #pragma unroll
    for (int i = 0; i < 4; i++)
        #pragma unroll
        for (int j = 0; j < 8; j++) acc[i][j] = 0.f;

    int wn = tid >> 2;          // 0..63
    int wk = (tid & 3) * 4;

    for (int kt = 0; kt < K; kt += 16) {
        // W tile: [64 n][16 k] -> Ws[k][n]
        float4 wv = *reinterpret_cast<const float4*>(&Wt[(size_t)(n0 + wn) * K + kt + wk]);
        Ws[wk + 0][wn] = wv.x; Ws[wk + 1][wn] = wv.y;
        Ws[wk + 2][wn] = wv.z; Ws[wk + 3][wn] = wv.w;
        // X tile: [128 m][16 k] -> Xs[k][m]
        #pragma unroll
        for (int q = 0; q < 2; q++) {
            int id2 = tid * 2 + q;
            int ml = id2 >> 2;
            int kq = (id2 & 3) * 4;
            float4 xv = *reinterpret_cast<const float4*>(&X[(size_t)(m0 + ml) * K + kt + kq]);
            Xs[kq + 0][ml] = xv.x; Xs[kq + 1][ml] = xv.y;
            Xs[kq + 2][ml] = xv.z; Xs[kq + 3][ml] = xv.w;
        }
        __syncthreads();
        #pragma unroll
        for (int k = 0; k < 16; k++) {
            float4 a  = *reinterpret_cast<const float4*>(&Ws[k][tx * 4]);
            float4 b0 = *reinterpret_cast<const float4*>(&Xs[k][ty * 8]);
            float4 b1 = *reinterpret_cast<const float4*>(&Xs[k][ty * 8 + 4]);
            float aa[4] = {a.x, a.y, a.z, a.w};
            float bb[8] = {b0.x, b0.y, b0.z, b0.w, b1.x, b1.y, b1.z, b1.w};
            #pragma unroll
            for (int i = 0; i < 4; i++)
                #pragma unroll
                for (int j = 0; j < 8; j++) acc[i][j] += aa[i] * bb[j];
        }
        __syncthreads();
    }
    float4 bz = *reinterpret_cast<const float4*>(&bias[n0 + tx * 4]);
    #pragma unroll
    for (int j = 0; j < 8; j++) {
        int m = m0 + ty * 8 + j;
        float4 v;
        v.x = acc[0][j] + bz.x; v.y = acc[1][j] + bz.y;
        v.z = acc[2][j] + bz.z; v.w = acc[3][j] + bz.w;
        *reinterpret_cast<float4*>(&C_[(size_t)m * N + n0 + tx * 4]) = v;
    }
}

// ---------------- windowed attention: one block per (window, head) -----------
__global__ __launch_bounds__(64)
void attn_kernel(const float* __restrict__ qkv, float* __restrict__ out) {
    __shared__ float qs[NTOK * 33];
    __shared__ float ks[NTOK * 33];
    __shared__ float vs[NTOK * 33];
    __shared__ float sc[NTOK * 51];
    int win  = blockIdx.x / HEADS;
    int head = blockIdx.x - win * HEADS;
    int tid = threadIdx.x;
    // load q,k,v tiles (49 x 32)
    for (int i = tid; i < NTOK * DH; i += 64) {
        int t = i >> 5;
        int d = i & 31;
        size_t rb = ((size_t)win * NTOK + t) * 576 + head * DH + d;
        qs[t * 33 + d] = qkv[rb];
        ks[t * 33 + d] = qkv[rb + 192];
        vs[t * 33 + d] = qkv[rb + 384];
    }
    __syncthreads();
    int i = tid;
    if (i < NTOK) {
        const float scale = 0.17677669529663687f; // 1/sqrt(32)
        float mx = -1e30f;
        for (int j = 0; j < NTOK; j++) {
            float dot = 0.f;
            #pragma unroll
            for (int d = 0; d < DH; d++) dot += qs[i * 33 + d] * ks[j * 33 + d];
            dot *= scale;
            sc[i * 51 + j] = dot;
            mx = fmaxf(mx, dot);
        }
        float sum = 0.f;
        for (int j = 0; j < NTOK; j++) {
            float e = expf(sc[i * 51 + j] - mx);
            sc[i * 51 + j] = e;
            sum += e;
        }
        float inv = 1.f / sum;
        float* op = out + ((size_t)win * NTOK + i) * CC + head * DH;
        #pragma unroll
        for (int d = 0; d < DH; d++) {
            float o = 0.f;
            for (int j = 0; j < NTOK; j++) o += sc[i * 51 + j] * vs[j * 33 + d];
            op[d] = o * inv;
        }
    }
}

// ---------------- un-window + roll(+3,+3) + residual --------------------------
__global__ __launch_bounds__(256)
void unwindow_residual(const float* __restrict__ x, const float* __restrict__ proj,
                       float* __restrict__ x1) {
    int idx = blockIdx.x * 256 + threadIdx.x;
    if (idx >= BB * CC * HWP) return;
    int b = idx / (CC * HWP);
    int r = idx - b * (CC * HWP);
    int c = r / HWP;
    int hw = r - c * HWP;
    int h = hw / WW;
    int w = hw - h * WW;
    int hr = h - 3; if (hr < 0) hr += HH;
    int wr = w - 3; if (wr < 0) wr += WW;
    int row = (b * 64 + (hr / WSZ) * NWH + (wr / WSZ)) * NTOK + (hr % WSZ) * WSZ + (wr % WSZ);
    x1[idx] = x[idx] + proj[(size_t)row * CC + c];
}

// ---------------- implicit-GEMM 3x3 conv --------------------------------------
// Tiles: 64 outch x 128 pixels x 16 K. MODE 0: bias+GELU; MODE 1: bias+residual.
__device__ __forceinline__ float gelu_exact(float v) {
    return 0.5f * v * (1.f + erff(v * 0.70710678118654752f));
}

template<int CIN, int COUT, int MODE>
__global__ __launch_bounds__(256)
void conv3x3(const float* __restrict__ in, const float* __restrict__ wgt,
             const float* __restrict__ bias, const float* __restrict__ res,
             float* __restrict__ out) {
    const int K = CIN * 9;
    __shared__ float As[16][68];
    __shared__ float Bs[16][132];
    int p0 = blockIdx.x * 128;
    int o0 = blockIdx.y * 64;
    int tid = threadIdx.x;
    int tx = tid & 15;   // outch group of 4
    int ty = tid >> 4;   // pixel group of 8
    float acc[4][8];
    #pragma unroll
    for (int i = 0; i < 4; i++)
        #pragma unroll
        for (int j = 0; j < 8; j++) acc[i][j] = 0.f;

    int wo = tid >> 2;
    int wk = (tid & 3) * 4;
    int rl = tid >> 4;          // 0..15 : k row in tile
    int pl = tid & 15;          // pixel lane; handles pixels pl + 16*i

    for (int kt = 0; kt < K; kt += 16) {
        // weight tile
        float4 wv = *reinterpret_cast<const float4*>(&wgt[(size_t)(o0 + wo) * K + kt + wk]);
        As[wk + 0][wo] = wv.x; As[wk + 1][wo] = wv.y;
        As[wk + 2][wo] = wv.z; As[wk + 3][wo] = wv.w;
        // gathered input tile
        int rr = kt + rl;
        int c  = rr / 9;
        int k9 = rr - c * 9;
        int kh = k9 / 3 - 1;
        int kw = k9 - (k9 / 3) * 3 - 1;
        #pragma unroll
        for (int i = 0; i < 8; i++) {
            int p  = p0 + pl + 16 * i;
            int b  = p / HWP;
            int hw = p - b * HWP;
            int h  = hw / WW;
            int w  = hw - h * WW;
            int hi = h + kh, wi = w + kw;
            float v = 0.f;
            if ((unsigned)hi < (unsigned)HH && (unsigned)wi < (unsigned)WW)
                v = in[((size_t)b * CIN + c) * HWP + hi * WW + wi];
            Bs[rl][pl + 16 * i] = v;
        }
        __syncthreads();
        #pragma unroll
        for (int k = 0; k < 16; k++) {
            float4 a  = *reinterpret_cast<const float4*>(&As[k][tx * 4]);
            float4 b0 = *reinterpret_cast<const float4*>(&Bs[k][ty * 8]);
            float4 b1 = *reinterpret_cast<const float4*>(&Bs[k][ty * 8 + 4]);
            float aa[4] = {a.x, a.y, a.z, a.w};
            float bb[8] = {b0.x, b0.y, b0.z, b0.w, b1.x, b1.y, b1.z, b1.w};
            #pragma unroll
            for (int i = 0; i < 4; i++)
                #pragma unroll
                for (int j = 0; j < 8; j++) acc[i][j] += aa[i] * bb[j];
        }
        __syncthreads();
    }

    float4 bz = *reinterpret_cast<const float4*>(&bias[o0 + tx * 4]);
    float bza[4] = {bz.x, bz.y, bz.z, bz.w};
    #pragma unroll
    for (int io = 0; io < 4; io++) {
        int o = o0 + tx * 4 + io;
        #pragma unroll
        for (int q = 0; q < 2; q++) {
            int p  = p0 + ty * 8 + 4 * q;            // quad start; never crosses batch (3136 % 4 == 0)
            int b  = p / HWP;
            int hw = p - b * HWP;
            size_t addr = ((size_t)b * COUT + o) * HWP + hw;
            float4 v;
            v.x = acc[io][4 * q + 0] + bza[io];
            v.y = acc[io][4 * q + 1] + bza[io];
            v.z = acc[io][4 * q + 2] + bza[io];
            v.w = acc[io][4 * q + 3] + bza[io];
            if (MODE == 0) {
                v.x = gelu_exact(v.x); v.y = gelu_exact(v.y);
                v.z = gelu_exact(v.z); v.w = gelu_exact(v.w);
            } else {
                float4 rv = *reinterpret_cast<const float4*>(&res[addr]);
                v.x += rv.x; v.y += rv.y; v.z += rv.z; v.w += rv.w;
            }
            *reinterpret_cast<float4*>(&out[addr]) = v;
        }
    }
}

// ---------------- launcher ----------------------------------------------------
extern "C" void kernel_launch(void* const* d_in, const int* in_sizes, int n_in,
                              void* d_out, int out_size) {
    const float* x       = (const float*)d_in[0];
    const float* ln1_g   = (const float*)d_in[1];
    const float* ln1_b   = (const float*)d_in[2];
    const float* qkv_w   = (const float*)d_in[3];
    const float* qkv_b   = (const float*)d_in[4];
    const float* proj_w  = (const float*)d_in[5];
    const float* proj_b  = (const float*)d_in[6];
    const float* ln2_g   = (const float*)d_in[7];
    const float* ln2_b   = (const float*)d_in[8];
    const float* conv1_w = (const float*)d_in[9];
    const float* conv1_b = (const float*)d_in[10];
    const float* conv2_w = (const float*)d_in[11];
    const float* conv2_b = (const float*)d_in[12];
    float* out = (float*)d_out;

    float* xw  = nullptr; cudaGetSymbolAddress((void**)&xw,  g_xw);
    float* qkv = nullptr; cudaGetSymbolAddress((void**)&qkv, g_qkv);
    float* att = nullptr; cudaGetSymbolAddress((void**)&att, g_attn);
    float* x1  = nullptr; cudaGetSymbolAddress((void**)&x1,  g_x1);
    float* ln2 = nullptr; cudaGetSymbolAddress((void**)&ln2, g_ln2);
    float* hid = nullptr; cudaGetSymbolAddress((void**)&hid, g_hid);

    // 1. LN1 + roll + window partition
    ln1_roll_window<<<NROWS / 256, 256>>>(x, ln1_g, ln1_b, xw);
    // 2. QKV GEMM: [100352,192] @ [576,192]^T
    gemm_nt<<<dim3(NROWS / 128, 576 / 64), 256>>>(xw, qkv_w, qkv_b, qkv, NROWS, 576, 192);
    // 3. per-(window,head) attention
    attn_kernel<<<NWIN * HEADS, 64>>>(qkv, att);
    // 4. proj GEMM (output reuses xw buffer)
    gemm_nt<<<dim3(NROWS / 128, 192 / 64), 256>>>(att, proj_w, proj_b, xw, NROWS, 192, 192);
    // 5. un-window + roll back + residual
    unwindow_residual<<<(BB * CC * HWP) / 256, 256>>>(x, xw, x1);
    // 6. LN2
    ln2_kernel<<<NROWS / 256, 256>>>(x1, ln2_g, ln2_b, ln2);
    // 7. conv1 192->768 + bias + GELU
    conv3x3<192, 768, 0><<<dim3(NROWS / 128, 768 / 64), 256>>>(ln2, conv1_w, conv1_b, nullptr, hid);
    // 8. conv2 768->192 + bias + residual -> out
    conv3x3<768, 192, 1><<<dim3(NROWS / 128, 192 / 64), 256>>>(hid, conv2_w, conv2_b, x1, out);
}

// round 3
// speedup vs baseline: 1.4901x; 1.4901x over previous
#include <cuda_runtime.h>
#include <cuda_bf16.h>
#include <math.h>

// ---------------- problem constants ----------------
#define BB 32
#define CC 192
#define HH 56
#define WW 56
#define HWP 3136            // 56*56
#define HEADS 6
#define DH 32               // head dim
#define WSZ 7
#define NWH 8               // windows per side
#define NWIN 2048           // 32*8*8
#define NTOK 49
#define NROWS 100352        // 2048*49 == 32*3136
#define HID 768
#define EPS_LN 1e-5f

// ---------------- scratch (static device globals) -----------------------------
__device__ __align__(128) float g_xw  [100352 * 192];
__device__ __align__(128) float g_qkv [100352 * 576];
__device__ __align__(128) float g_attn[100352 * 192];
__device__ __align__(128) float g_x1  [19267584];
__device__ __align__(128) float g_ln2 [19267584];
__device__ __align__(128) float g_hid [32 * 768 * 3136];
// split bf16 weights (hi/lo) for the two convs; both are 1,327,104 elements
__device__ __align__(128) __nv_bfloat16 g_w1h[1327104], g_w1l[1327104];
__device__ __align__(128) __nv_bfloat16 g_w2h[1327104], g_w2l[1327104];

// ---------------- weight split: fp32 -> bf16 hi + bf16 lo ---------------------
__global__ __launch_bounds__(256)
void split_weights(const float* __restrict__ w, __nv_bfloat16* __restrict__ hi,
                   __nv_bfloat16* __restrict__ lo, int n) {
    int i = blockIdx.x * 256 + threadIdx.x;
    if (i >= n) return;
    float v = w[i];
    __nv_bfloat16 h = __float2bfloat16(v);
    hi[i] = h;
    lo[i] = __float2bfloat16(v - __bfloat162float(h));
}

// ---------------- LN1 + roll(-3,-3) + window partition -----------------------
__global__ __launch_bounds__(256)
void ln1_roll_window(const float* __restrict__ x, const float* __restrict__ g,
                     const float* __restrict__ bt, float* __restrict__ xw) {
    int idx = blockIdx.x * 256 + threadIdx.x;
    if (idx >= NROWS) return;
    int bb = idx / HWP;
    int hw = idx - bb * HWP;
    int h1 = hw / WW;
    int w1 = hw - h1 * WW;
    int hs = h1 + 3; if (hs >= HH) hs -= HH;
    int ws = w1 + 3; if (ws >= WW) ws -= WW;
    const float* xp = x + (size_t)bb * CC * HWP + hs * WW + ws;
    float s = 0.f, ss = 0.f;
    #pragma unroll 4
    for (int c = 0; c < CC; c++) { float v = xp[(size_t)c * HWP]; s += v; ss += v * v; }
    float mean = s * (1.f / CC);
    float var  = ss * (1.f / CC) - mean * mean;
    float rstd = rsqrtf(var + EPS_LN);
    int win = bb * 64 + (h1 / WSZ) * NWH + (w1 / WSZ);
    int t   = (h1 % WSZ) * WSZ + (w1 % WSZ);
    float* op = xw + ((size_t)win * NTOK + t) * CC;
    #pragma unroll 4
    for (int c = 0; c < CC; c++)
        op[c] = (xp[(size_t)c * HWP] - mean) * rstd * g[c] + bt[c];
}

// ---------------- LN2 ---------------------------------------------------------
__global__ __launch_bounds__(256)
void ln2_kernel(const float* __restrict__ x, const float* __restrict__ g,
                const float* __restrict__ bt, float* __restrict__ out) {
    int idx = blockIdx.x * 256 + threadIdx.x;
    if (idx >= NROWS) return;
    int bb = idx / HWP;
    int hw = idx - bb * HWP;
    const float* xp = x + (size_t)bb * CC * HWP + hw;
    float s = 0.f, ss = 0.f;
    #pragma unroll 4
    for (int c = 0; c < CC; c++) { float v = xp[(size_t)c * HWP]; s += v; ss += v * v; }
    float mean = s * (1.f / CC);
    float var  = ss * (1.f / CC) - mean * mean;
    float rstd = rsqrtf(var + EPS_LN);
    float* op = out + (size_t)bb * CC * HWP + hw;
    #pragma unroll 4
    for (int c = 0; c < CC; c++)
        op[(size_t)c * HWP] = (xp[(size_t)c * HWP] - mean) * rstd * g[c] + bt[c];
}

// ---------------- NT SGEMM (qkv / proj) ---------------------------------------
__global__ __launch_bounds__(256)
void gemm_nt(const float* __restrict__ X, const float* __restrict__ Wt,
             const float* __restrict__ bias, float* __restrict__ C_,
             int M, int N, int K) {
    __shared__ float Ws[16][68];
    __shared__ float Xs[16][132];
    int m0 = blockIdx.x * 128;
    int n0 = blockIdx.y * 64;
    int tid = threadIdx.x;
    int tx = tid & 15;
    int ty = tid >> 4;
    float acc[4][8];
    #pragma unroll
    for (int i = 0; i < 4; i++)
        #pragma unroll
        for (int j = 0; j < 8; j++) acc[i][j] = 0.f;

    int wn = tid >> 2;
    int wk = (tid & 3) * 4;

    for (int kt = 0; kt < K; kt += 16) {
        float4 wv = *reinterpret_cast<const float4*>(&Wt[(size_t)(n0 + wn) * K + kt + wk]);
        Ws[wk + 0][wn] = wv.x; Ws[wk + 1][wn] = wv.y;
        Ws[wk + 2][wn] = wv.z; Ws[wk + 3][wn] = wv.w;
        #pragma unroll
        for (int q = 0; q < 2; q++) {
            int id2 = tid * 2 + q;
            int ml = id2 >> 2;
            int kq = (id2 & 3) * 4;
            float4 xv = *reinterpret_cast<const float4*>(&X[(size_t)(m0 + ml) * K + kt + kq]);
            Xs[kq + 0][ml] = xv.x; Xs[kq + 1][ml] = xv.y;
            Xs[kq + 2][ml] = xv.z; Xs[kq + 3][ml] = xv.w;
        }
        __syncthreads();
        #pragma unroll
        for (int k = 0; k < 16; k++) {
            float4 a  = *reinterpret_cast<const float4*>(&Ws[k][tx * 4]);
            float4 b0 = *reinterpret_cast<const float4*>(&Xs[k][ty * 8]);
            float4 b1 = *reinterpret_cast<const float4*>(&Xs[k][ty * 8 + 4]);
            float aa[4] = {a.x, a.y, a.z, a.w};
            float bb[8] = {b0.x, b0.y, b0.z, b0.w, b1.x, b1.y, b1.z, b1.w};
            #pragma unroll
            for (int i = 0; i < 4; i++)
                #pragma unroll
                for (int j = 0; j < 8; j++) acc[i][j] += aa[i] * bb[j];
        }
        __syncthreads();
    }
    float4 bz = *reinterpret_cast<const float4*>(&bias[n0 + tx * 4]);
    #pragma unroll
    for (int j = 0; j < 8; j++) {
        int m = m0 + ty * 8 + j;
        float4 v;
        v.x = acc[0][j] + bz.x; v.y = acc[1][j] + bz.y;
        v.z = acc[2][j] + bz.z; v.w = acc[3][j] + bz.w;
        *reinterpret_cast<float4*>(&C_[(size_t)m * N + n0 + tx * 4]) = v;
    }
}

// ---------------- windowed attention ------------------------------------------
__global__ __launch_bounds__(64)
void attn_kernel(const float* __restrict__ qkv, float* __restrict__ out) {
    __shared__ float qs[NTOK * 33];
    __shared__ float ks[NTOK * 33];
    __shared__ float vs[NTOK * 33];
    __shared__ float sc[NTOK * 51];
    int win  = blockIdx.x / HEADS;
    int head = blockIdx.x - win * HEADS;
    int tid = threadIdx.x;
    for (int i = tid; i < NTOK * DH; i += 64) {
        int t = i >> 5;
        int d = i & 31;
        size_t rb = ((size_t)win * NTOK + t) * 576 + head * DH + d;
        qs[t * 33 + d] = qkv[rb];
        ks[t * 33 + d] = qkv[rb + 192];
        vs[t * 33 + d] = qkv[rb + 384];
    }
    __syncthreads();
    int i = tid;
    if (i < NTOK) {
        const float scale = 0.17677669529663687f;
        float mx = -1e30f;
        for (int j = 0; j < NTOK; j++) {
            float dot = 0.f;
            #pragma unroll
            for (int d = 0; d < DH; d++) dot += qs[i * 33 + d] * ks[j * 33 + d];
            dot *= scale;
            sc[i * 51 + j] = dot;
            mx = fmaxf(mx, dot);
        }
        float sum = 0.f;
        for (int j = 0; j < NTOK; j++) {
            float e = expf(sc[i * 51 + j] - mx);
            sc[i * 51 + j] = e;
            sum += e;
        }
        float inv = 1.f / sum;
        float* op = out + ((size_t)win * NTOK + i) * CC + head * DH;
        #pragma unroll
        for (int d = 0; d < DH; d++) {
            float o = 0.f;
            for (int j = 0; j < NTOK; j++) o += sc[i * 51 + j] * vs[j * 33 + d];
            op[d] = o * inv;
        }
    }
}

// ---------------- un-window + roll(+3,+3) + residual ---------------------------
__global__ __launch_bounds__(256)
void unwindow_residual(const float* __restrict__ x, const float* __restrict__ proj,
                       float* __restrict__ x1) {
    int idx = blockIdx.x * 256 + threadIdx.x;
    if (idx >= BB * CC * HWP) return;
    int b = idx / (CC * HWP);
    int r = idx - b * (CC * HWP);
    int c = r / HWP;
    int hw = r - c * HWP;
    int h = hw / WW;
    int w = hw - h * WW;
    int hr = h - 3; if (hr < 0) hr += HH;
    int wr = w - 3; if (wr < 0) wr += WW;
    int row = (b * 64 + (hr / WSZ) * NWH + (wr / WSZ)) * NTOK + (hr % WSZ) * WSZ + (wr % WSZ);
    x1[idx] = x[idx] + proj[(size_t)row * CC + c];
}

// ---------------- bf16 split-MMA implicit-GEMM 3x3 conv ------------------------
__device__ __forceinline__ float gelu_exact(float v) {
    return 0.5f * v * (1.f + erff(v * 0.70710678118654752f));
}

__device__ __forceinline__ void mma_bf16(float* c, const unsigned* a, const unsigned* b) {
    asm volatile(
        "mma.sync.aligned.m16n8k16.row.col.f32.bf16.bf16.f32 "
        "{%0,%1,%2,%3}, {%4,%5,%6,%7}, {%8,%9}, {%0,%1,%2,%3};\n"
        : "+f"(c[0]), "+f"(c[1]), "+f"(c[2]), "+f"(c[3])
        : "r"(a[0]), "r"(a[1]), "r"(a[2]), "r"(a[3]), "r"(b[0]), "r"(b[1]));
}

// block tile: 64 outch x 128 pixels, k-chunk 16. 8 warps: 2(m) x 4(n), warp 32x32.
// C = Whi*Xhi + Whi*Xlo + Wlo*Xhi, fp32 accum.  MODE 0: bias+GELU; 1: bias+residual.
template<int CIN, int COUT, int MODE>
__global__ __launch_bounds__(256)
void conv3x3_mma(const float* __restrict__ in,
                 const __nv_bfloat16* __restrict__ whi, const __nv_bfloat16* __restrict__ wlo,
                 const float* __restrict__ bias, const float* __restrict__ res,
                 float* __restrict__ out) {
    const int K = CIN * 9;
    __shared__ __nv_bfloat16 Ah[64][20], Al[64][20];     // [outch][k16] (pad 20)
    __shared__ __nv_bfloat16 Bh[128][18], Bl[128][18];   // [pixel][k16] (pad 18)

    int p0 = blockIdx.x * 128;
    int o0 = blockIdx.y * 64;
    int tid  = threadIdx.x;
    int lane = tid & 31;
    int wrp  = tid >> 5;
    int wm = wrp & 1;          // m (outch) warp
    int wn = wrp >> 1;         // n (pixel) warp

    float acc[2][4][4];
    #pragma unroll
    for (int a = 0; a < 2; a++)
        #pragma unroll
        for (int b = 0; b < 4; b++)
            #pragma unroll
            for (int c = 0; c < 4; c++) acc[a][b][c] = 0.f;

    // A staging: thread -> (outch row, 4 k)
    int ao = tid >> 2;
    int ak = (tid & 3) * 4;
    // B staging: thread -> (k row rl, pixels pl + 16*i)
    int rl = tid >> 4;
    int pl = tid & 15;
    int pb[8], ph[8], pw_[8];
    #pragma unroll
    for (int i = 0; i < 8; i++) {
        int p  = p0 + pl + 16 * i;
        int b  = p / HWP;
        int hw = p - b * HWP;
        pb[i]  = b;
        ph[i]  = hw / WW;
        pw_[i] = hw - ph[i] * WW;
    }

    int r  = lane >> 2;
    int c2 = (lane & 3) * 2;

    for (int kt = 0; kt < K; kt += 16) {
        // stage weights (4 halves = 8B per thread, per array)
        *reinterpret_cast<uint2*>(&Ah[ao][ak]) =
            *reinterpret_cast<const uint2*>(&whi[(size_t)(o0 + ao) * K + kt + ak]);
        *reinterpret_cast<uint2*>(&Al[ao][ak]) =
            *reinterpret_cast<const uint2*>(&wlo[(size_t)(o0 + ao) * K + kt + ak]);
        // stage gathered input, split hi/lo
        int rr = kt + rl;
        int cch = rr / 9;
        int k9  = rr - cch * 9;
        int kh  = k9 / 3 - 1;
        int kw  = k9 - (k9 / 3) * 3 - 1;
        #pragma unroll
        for (int i = 0; i < 8; i++) {
            int hi_ = ph[i] + kh, wi = pw_[i] + kw;
            float v = 0.f;
            if ((unsigned)hi_ < (unsigned)HH && (unsigned)wi < (unsigned)WW)
                v = in[((size_t)pb[i] * CIN + cch) * HWP + hi_ * WW + wi];
            __nv_bfloat16 vh = __float2bfloat16(v);
            Bh[pl + 16 * i][rl] = vh;
            Bl[pl + 16 * i][rl] = __float2bfloat16(v - __bfloat162float(vh));
        }
        __syncthreads();

        // A fragments for both m-tiles
        unsigned ahi[2][4], alo[2][4];
        #pragma unroll
        for (int mt = 0; mt < 2; mt++) {
            int mb = wm * 32 + mt * 16;
            ahi[mt][0] = *reinterpret_cast<unsigned*>(&Ah[mb + r][c2]);
            ahi[mt][1] = *reinterpret_cast<unsigned*>(&Ah[mb + r + 8][c2]);
            ahi[mt][2] = *reinterpret_cast<unsigned*>(&Ah[mb + r][c2 + 8]);
            ahi[mt][3] = *reinterpret_cast<unsigned*>(&Ah[mb + r + 8][c2 + 8]);
            alo[mt][0] = *reinterpret_cast<unsigned*>(&Al[mb + r][c2]);
            alo[mt][1] = *reinterpret_cast<unsigned*>(&Al[mb + r + 8][c2]);
            alo[mt][2] = *reinterpret_cast<unsigned*>(&Al[mb + r][c2 + 8]);
            alo[mt][3] = *reinterpret_cast<unsigned*>(&Al[mb + r + 8][c2 + 8]);
        }
        #pragma unroll
        for (int nt = 0; nt < 4; nt++) {
            int nb = wn * 32 + nt * 8 + (lane >> 2);
            unsigned bhv[2], blv[2];
            bhv[0] = *reinterpret_cast<unsigned*>(&Bh[nb][c2]);
            bhv[1] = *reinterpret_cast<unsigned*>(&Bh[nb][c2 + 8]);
            blv[0] = *reinterpret_cast<unsigned*>(&Bl[nb][c2]);
            blv[1] = *reinterpret_cast<unsigned*>(&Bl[nb][c2 + 8]);
            #pragma unroll
            for (int mt = 0; mt < 2; mt++) {
                mma_bf16(acc[mt][nt], ahi[mt], bhv);
                mma_bf16(acc[mt][nt], ahi[mt], blv);
                mma_bf16(acc[mt][nt], alo[mt], bhv);
            }
        }
        __syncthreads();
    }

    // epilogue: C frag (m16n8): rows r, r+8; cols c2, c2+1
    #pragma unroll
    for (int mt = 0; mt < 2; mt++) {
        int obase = o0 + wm * 32 + mt * 16;
        float bz0 = bias[obase + r];
        float bz1 = bias[obase + r + 8];
        #pragma unroll
        for (int nt = 0; nt < 4; nt++) {
            int p  = p0 + wn * 32 + nt * 8 + c2;     // even pixel; pair p, p+1
            int b  = p / HWP;
            int hw = p - b * HWP;                    // pair never crosses batch (even HWP)
            #pragma unroll
            for (int half = 0; half < 2; half++) {
                int o = obase + r + half * 8;
                float v0 = acc[mt][nt][half * 2 + 0] + (half ? bz1 : bz0);
                float v1 = acc[mt][nt][half * 2 + 1] + (half ? bz1 : bz0);
                size_t addr = ((size_t)b * COUT + o) * HWP + hw;
                float2 v;
                if (MODE == 0) {
                    v.x = gelu_exact(v0); v.y = gelu_exact(v1);
                } else {
                    const float2 rv = *reinterpret_cast<const float2*>(&res[addr]);
                    v.x = v0 + rv.x; v.y = v1 + rv.y;
                }
                *reinterpret_cast<float2*>(&out[addr]) = v;
            }
        }
    }
}

// ---------------- launcher ----------------------------------------------------
extern "C" void kernel_launch(void* const* d_in, const int* in_sizes, int n_in,
                              void* d_out, int out_size) {
    const float* x       = (const float*)d_in[0];
    const float* ln1_g   = (const float*)d_in[1];
    const float* ln1_b   = (const float*)d_in[2];
    const float* qkv_w   = (const float*)d_in[3];
    const float* qkv_b   = (const float*)d_in[4];
    const float* proj_w  = (const float*)d_in[5];
    const float* proj_b  = (const float*)d_in[6];
    const float* ln2_g   = (const float*)d_in[7];
    const float* ln2_b   = (const float*)d_in[8];
    const float* conv1_w = (const float*)d_in[9];
    const float* conv1_b = (const float*)d_in[10];
    const float* conv2_w = (const float*)d_in[11];
    const float* conv2_b = (const float*)d_in[12];
    float* out = (float*)d_out;

    float* xw  = nullptr; cudaGetSymbolAddress((void**)&xw,  g_xw);
    float* qkv = nullptr; cudaGetSymbolAddress((void**)&qkv, g_qkv);
    float* att = nullptr; cudaGetSymbolAddress((void**)&att, g_attn);
    float* x1  = nullptr; cudaGetSymbolAddress((void**)&x1,  g_x1);
    float* ln2 = nullptr; cudaGetSymbolAddress((void**)&ln2, g_ln2);
    float* hid = nullptr; cudaGetSymbolAddress((void**)&hid, g_hid);
    __nv_bfloat16 *w1h, *w1l, *w2h, *w2l;
    cudaGetSymbolAddress((void**)&w1h, g_w1h);
    cudaGetSymbolAddress((void**)&w1l, g_w1l);
    cudaGetSymbolAddress((void**)&w2h, g_w2h);
    cudaGetSymbolAddress((void**)&w2l, g_w2l);

    const int NW = 1327104;  // both conv weight tensors
    split_weights<<<(NW + 255) / 256, 256>>>(conv1_w, w1h, w1l, NW);
    split_weights<<<(NW + 255) / 256, 256>>>(conv2_w, w2h, w2l, NW);

    ln1_roll_window<<<NROWS / 256, 256>>>(x, ln1_g, ln1_b, xw);
    gemm_nt<<<dim3(NROWS / 128, 576 / 64), 256>>>(xw, qkv_w, qkv_b, qkv, NROWS, 576, 192);
    attn_kernel<<<NWIN * HEADS, 64>>>(qkv, att);
    gemm_nt<<<dim3(NROWS / 128, 192 / 64), 256>>>(att, proj_w, proj_b, xw, NROWS, 192, 192);
    unwindow_residual<<<(BB * CC * HWP) / 256, 256>>>(x, xw, x1);
    ln2_kernel<<<NROWS / 256, 256>>>(x1, ln2_g, ln2_b, ln2);

    conv3x3_mma<192, 768, 0><<<dim3(NROWS / 128, 768 / 64), 256>>>(ln2, w1h, w1l, conv1_b, nullptr, hid);
    conv3x3_mma<768, 192, 1><<<dim3(NROWS / 128, 192 / 64), 256>>>(hid, w2h, w2l, conv2_b, x1, out);
}

// round 5
// speedup vs baseline: 2.5546x; 1.7144x over previous
#include <cuda_runtime.h>
#include <cuda_fp16.h>
#include <math.h>
#include <stdint.h>

// ---------------- problem constants ----------------
#define BB 32
#define CC 192
#define HH 56
#define WW 56
#define HWP 3136            // 56*56
#define HEADS 6
#define DH 32
#define WSZ 7
#define NWH 8
#define NWIN 2048
#define NTOK 49
#define NROWS 100352        // 32*3136
#define HID 768
#define EPS_LN 1e-5f

// ---------------- scratch (static device globals) -----------------------------
__device__ __align__(128) float g_xw  [100352 * 192];
__device__ __align__(128) float g_qkv [100352 * 576];
__device__ __align__(128) float g_attn[100352 * 192];
__device__ __align__(128) float g_x1  [19267584];
// NHWC fp16 hi/lo activations
__device__ __align__(128) __half g_ah[100352 * 192], g_al[100352 * 192];   // ln2 out
__device__ __align__(128) __half g_hh[100352 * 768], g_hl[100352 * 768];   // conv1 out
// tap-major split fp16 weights: [O][tap][Cin]
__device__ __align__(128) __half g_w1h[1327104], g_w1l[1327104];
__device__ __align__(128) __half g_w2h[1327104], g_w2l[1327104];

// ---------------- small helpers ------------------------------------------------
__device__ __forceinline__ uint32_t smem_u32(const void* p) {
    uint32_t a;
    asm("{ .reg .u64 t; cvta.to.shared.u64 t, %1; cvt.u32.u64 %0, t; }" : "=r"(a) : "l"(p));
    return a;
}
__device__ __forceinline__ void cp16(uint32_t dst, const void* src, bool pred) {
    int sz = pred ? 16 : 0;
    asm volatile("cp.async.cg.shared.global [%0], [%1], 16, %2;"
                 :: "r"(dst), "l"(src), "r"(sz) : "memory");
}
#define CP_COMMIT() asm volatile("cp.async.commit_group;" ::: "memory")
#define CP_WAIT(N)  asm volatile("cp.async.wait_group %0;" :: "n"(N) : "memory")

#define LDSM4(r, a)                                                              \
    asm volatile("ldmatrix.sync.aligned.m8n8.x4.shared.b16 {%0,%1,%2,%3}, [%4];" \
                 : "=r"((r)[0]), "=r"((r)[1]), "=r"((r)[2]), "=r"((r)[3]) : "r"(a))

__device__ __forceinline__ void mma_fp16(float* c, const unsigned* a, const unsigned* b) {
    asm volatile(
        "mma.sync.aligned.m16n8k16.row.col.f32.f16.f16.f32 "
        "{%0,%1,%2,%3}, {%4,%5,%6,%7}, {%8,%9}, {%0,%1,%2,%3};\n"
        : "+f"(c[0]), "+f"(c[1]), "+f"(c[2]), "+f"(c[3])
        : "r"(a[0]), "r"(a[1]), "r"(a[2]), "r"(a[3]), "r"(b[0]), "r"(b[1]));
}

__device__ __forceinline__ float gelu_exact(float v) {
    return 0.5f * v * (1.f + erff(v * 0.70710678118654752f));
}

// ---------------- weight split + tap-major reorder -----------------------------
// in: [O][I][3][3] fp32  ->  out hi/lo: [O][tap(9)][I] fp16
__global__ __launch_bounds__(256)
void split_w(const float* __restrict__ w, __half* __restrict__ hi,
             __half* __restrict__ lo, int O, int I) {
    int idx = blockIdx.x * 256 + threadIdx.x;
    int n = O * I * 9;
    if (idx >= n) return;
    int o = idx / (I * 9);
    int rem = idx - o * (I * 9);
    int i = rem / 9;
    int tap = rem - i * 9;
    float v = w[idx];
    __half h = __float2half(v);
    int dst = o * (9 * I) + tap * I + i;
    hi[dst] = h;
    lo[dst] = __float2half(v - __half2float(h));
}

// ---------------- LN1 + roll(-3,-3) + window partition -------------------------
__global__ __launch_bounds__(256)
void ln1_roll_window(const float* __restrict__ x, const float* __restrict__ g,
                     const float* __restrict__ bt, float* __restrict__ xw) {
    int idx = blockIdx.x * 256 + threadIdx.x;
    if (idx >= NROWS) return;
    int bb = idx / HWP;
    int hw = idx - bb * HWP;
    int h1 = hw / WW;
    int w1 = hw - h1 * WW;
    int hs = h1 + 3; if (hs >= HH) hs -= HH;
    int ws = w1 + 3; if (ws >= WW) ws -= WW;
    const float* xp = x + (size_t)bb * CC * HWP + hs * WW + ws;
    float s = 0.f, ss = 0.f;
    #pragma unroll 4
    for (int c = 0; c < CC; c++) { float v = xp[(size_t)c * HWP]; s += v; ss += v * v; }
    float mean = s * (1.f / CC);
    float var  = ss * (1.f / CC) - mean * mean;
    float rstd = rsqrtf(var + EPS_LN);
    int win = bb * 64 + (h1 / WSZ) * NWH + (w1 / WSZ);
    int t   = (h1 % WSZ) * WSZ + (w1 % WSZ);
    float* op = xw + ((size_t)win * NTOK + t) * CC;
    #pragma unroll 4
    for (int c = 0; c < CC; c++)
        op[c] = (xp[(size_t)c * HWP] - mean) * rstd * g[c] + bt[c];
}

// ---------------- LN2: NCHW fp32 -> NHWC fp16 hi/lo ----------------------------
__global__ __launch_bounds__(256)
void ln2_nhwc(const float* __restrict__ x, const float* __restrict__ g,
              const float* __restrict__ bt, __half* __restrict__ oh,
              __half* __restrict__ ol) {
    int idx = blockIdx.x * 256 + threadIdx.x;
    if (idx >= NROWS) return;
    int bb = idx / HWP;
    int hw = idx - bb * HWP;
    const float* xp = x + (size_t)bb * CC * HWP + hw;
    float s = 0.f, ss = 0.f;
    #pragma unroll 4
    for (int c = 0; c < CC; c++) { float v = xp[(size_t)c * HWP]; s += v; ss += v * v; }
    float mean = s * (1.f / CC);
    float var  = ss * (1.f / CC) - mean * mean;
    float rstd = rsqrtf(var + EPS_LN);
    __half* ph = oh + (size_t)idx * CC;
    __half* pl = ol + (size_t)idx * CC;
    #pragma unroll 4
    for (int c = 0; c < CC; c++) {
        float v = (xp[(size_t)c * HWP] - mean) * rstd * g[c] + bt[c];
        __half h = __float2half(v);
        ph[c] = h;
        pl[c] = __float2half(v - __half2float(h));
    }
}

// ---------------- NT SGEMM (qkv / proj) ----------------------------------------
__global__ __launch_bounds__(256)
void gemm_nt(const float* __restrict__ X, const float* __restrict__ Wt,
             const float* __restrict__ bias, float* __restrict__ C_,
             int M, int N, int K) {
    __shared__ float Ws[16][68];
    __shared__ float Xs[16][132];
    int m0 = blockIdx.x * 128;
    int n0 = blockIdx.y * 64;
    int tid = threadIdx.x;
    int tx = tid & 15;
    int ty = tid >> 4;
    float acc[4][8];
    #pragma unroll
    for (int i = 0; i < 4; i++)
        #pragma unroll
        for (int j = 0; j < 8; j++) acc[i][j] = 0.f;
    int wn = tid >> 2;
    int wk = (tid & 3) * 4;
    for (int kt = 0; kt < K; kt += 16) {
        float4 wv = *reinterpret_cast<const float4*>(&Wt[(size_t)(n0 + wn) * K + kt + wk]);
        Ws[wk + 0][wn] = wv.x; Ws[wk + 1][wn] = wv.y;
        Ws[wk + 2][wn] = wv.z; Ws[wk + 3][wn] = wv.w;
        #pragma unroll
        for (int q = 0; q < 2; q++) {
            int id2 = tid * 2 + q;
            int ml = id2 >> 2;
            int kq = (id2 & 3) * 4;
            float4 xv = *reinterpret_cast<const float4*>(&X[(size_t)(m0 + ml) * K + kt + kq]);
            Xs[kq + 0][ml] = xv.x; Xs[kq + 1][ml] = xv.y;
            Xs[kq + 2][ml] = xv.z; Xs[kq + 3][ml] = xv.w;
        }
        __syncthreads();
        #pragma unroll
        for (int k = 0; k < 16; k++) {
            float4 a  = *reinterpret_cast<const float4*>(&Ws[k][tx * 4]);
            float4 b0 = *reinterpret_cast<const float4*>(&Xs[k][ty * 8]);
            float4 b1 = *reinterpret_cast<const float4*>(&Xs[k][ty * 8 + 4]);
            float aa[4] = {a.x, a.y, a.z, a.w};
            float bb[8] = {b0.x, b0.y, b0.z, b0.w, b1.x, b1.y, b1.z, b1.w};
            #pragma unroll
            for (int i = 0; i < 4; i++)
                #pragma unroll
                for (int j = 0; j < 8; j++) acc[i][j] += aa[i] * bb[j];
        }
        __syncthreads();
    }
    float4 bz = *reinterpret_cast<const float4*>(&bias[n0 + tx * 4]);
    #pragma unroll
    for (int j = 0; j < 8; j++) {
        int m = m0 + ty * 8 + j;
        float4 v;
        v.x = acc[0][j] + bz.x; v.y = acc[1][j] + bz.y;
        v.z = acc[2][j] + bz.z; v.w = acc[3][j] + bz.w;
        *reinterpret_cast<float4*>(&C_[(size_t)m * N + n0 + tx * 4]) = v;
    }
}

// ---------------- windowed attention -------------------------------------------
__global__ __launch_bounds__(64)
void attn_kernel(const float* __restrict__ qkv, float* __restrict__ out) {
    __shared__ float qs[NTOK * 33];
    __shared__ float ks[NTOK * 33];
    __shared__ float vs[NTOK * 33];
    __shared__ float sc[NTOK * 51];
    int win  = blockIdx.x / HEADS;
    int head = blockIdx.x - win * HEADS;
    int tid = threadIdx.x;
    for (int i = tid; i < NTOK * DH; i += 64) {
        int t = i >> 5;
        int d = i & 31;
        size_t rb = ((size_t)win * NTOK + t) * 576 + head * DH + d;
        qs[t * 33 + d] = qkv[rb];
        ks[t * 33 + d] = qkv[rb + 192];
        vs[t * 33 + d] = qkv[rb + 384];
    }
    __syncthreads();
    int i = tid;
    if (i < NTOK) {
        const float scale = 0.17677669529663687f;
        float mx = -1e30f;
        for (int j = 0; j < NTOK; j++) {
            float dot = 0.f;
            #pragma unroll
            for (int d = 0; d < DH; d++) dot += qs[i * 33 + d] * ks[j * 33 + d];
            dot *= scale;
            sc[i * 51 + j] = dot;
            mx = fmaxf(mx, dot);
        }
        float sum = 0.f;
        for (int j = 0; j < NTOK; j++) {
            float e = expf(sc[i * 51 + j] - mx);
            sc[i * 51 + j] = e;
            sum += e;
        }
        float inv = 1.f / sum;
        float* op = out + ((size_t)win * NTOK + i) * CC + head * DH;
        #pragma unroll
        for (int d = 0; d < DH; d++) {
            float o = 0.f;
            for (int j = 0; j < NTOK; j++) o += sc[i * 51 + j] * vs[j * 33 + d];
            op[d] = o * inv;
        }
    }
}

// ---------------- un-window + roll + residual ----------------------------------
__global__ __launch_bounds__(256)
void unwindow_residual(const float* __restrict__ x, const float* __restrict__ proj,
                       float* __restrict__ x1) {
    int idx = blockIdx.x * 256 + threadIdx.x;
    if (idx >= BB * CC * HWP) return;
    int b = idx / (CC * HWP);
    int r = idx - b * (CC * HWP);
    int c = r / HWP;
    int hw = r - c * HWP;
    int h = hw / WW;
    int w = hw - h * WW;
    int hr = h - 3; if (hr < 0) hr += HH;
    int wr = w - 3; if (wr < 0) wr += WW;
    int row = (b * 64 + (hr / WSZ) * NWH + (wr / WSZ)) * NTOK + (hr % WSZ) * WSZ + (wr % WSZ);
    x1[idx] = x[idx] + proj[(size_t)row * CC + c];
}

// ---------------- fp16 HMMA implicit-GEMM 3x3 conv -----------------------------
// Block: 128 px (m) x NT oc (n). 8 warps (2m x 4n), warp tile 64x(NT/4).
// K chunks of 32 (tap-major). 3 MMAs per frag pair: Wh*Xh + Wh*Xl + Wl*Xh.
// MODE 0: bias+GELU -> NHWC fp16 hi/lo. MODE 1: bias+residual -> NCHW fp32.
template<int CIN, int COUT, int NT, int MODE>
__global__ __launch_bounds__(256, 1)
void conv3x3_hmma(const __half* __restrict__ xh, const __half* __restrict__ xl,
                  const __half* __restrict__ wh, const __half* __restrict__ wl,
                  const float* __restrict__ bias, const float* __restrict__ res,
                  float* __restrict__ outf, __half* __restrict__ outh,
                  __half* __restrict__ outl) {
    constexpr int K      = CIN * 9;
    constexpr int NC     = K / 32;          // chunks
    constexpr int CPT    = CIN / 32;        // chunks per tap
    constexpr int NTW    = NT / 4 / 8;      // n-tiles (n8) per warp
    constexpr int NPAIR  = NTW / 2;
    constexpr int ARLD   = 40;              // smem row stride in halves (80B)
    constexpr int A_HALF = 128 * ARLD;      // per array
    constexpr int W_HALF = NT * ARLD;
    constexpr int STG    = 2 * A_HALF + 2 * W_HALF;   // halves per stage

    extern __shared__ __half sm[];
    int tid  = threadIdx.x;
    int lane = tid & 31;
    int wid  = tid >> 5;
    int wm = wid & 1;          // 0..1 : px row block of 64
    int wn = wid >> 1;         // 0..3 : oc block of NT/4
    int p0 = blockIdx.x * 128;
    int o0 = blockIdx.y * NT;

    // per-thread staging rows (A): rows r0 = tid>>2 and r0+64; seg = tid&3
    int ar0 = tid >> 2;
    int seg = tid & 3;
    int pxA[2], bA[2], hA[2], wA[2];
    #pragma unroll
    for (int q = 0; q < 2; q++) {
        int px = p0 + ar0 + q * 64;
        int b  = px / HWP;
        int hw = px - b * HWP;
        pxA[q] = px; bA[q] = b; hA[q] = hw / WW; wA[q] = hw - (hw / WW) * WW;
    }

    auto load_stage = [&](int ci, int s) {
        __half* st = sm + s * STG;
        uint32_t uAh = smem_u32(st);
        uint32_t uAl = uAh + A_HALF * 2;
        uint32_t uWh = uAl + A_HALF * 2;
        uint32_t uWl = uWh + W_HALF * 2;
        int tap = ci / CPT;
        int c0  = (ci - tap * CPT) * 32;
        int kh = tap / 3 - 1, kw = tap - (tap / 3) * 3 - 1;
        int kt = ci * 32;
        // A tiles
        #pragma unroll
        for (int q = 0; q < 2; q++) {
            int row = ar0 + q * 64;
            int h2 = hA[q] + kh, w2 = wA[q] + kw;
            bool ok = ((unsigned)h2 < (unsigned)HH) && ((unsigned)w2 < (unsigned)WW);
            size_t off = ((size_t)(bA[q] * HWP + h2 * WW + w2)) * CIN + c0 + seg * 8;
            const __half* sh = ok ? xh + off : xh;
            const __half* sl = ok ? xl + off : xl;
            cp16(uAh + (row * ARLD + seg * 8) * 2, sh, ok);
            cp16(uAl + (row * ARLD + seg * 8) * 2, sl, ok);
        }
        // W tiles
        #pragma unroll
        for (int j = 0; j < NT / 64; j++) {
            int row = j * 64 + ar0;
            size_t off = (size_t)(o0 + row) * K + kt + seg * 8;
            cp16(uWh + (row * ARLD + seg * 8) * 2, wh + off, true);
            cp16(uWl + (row * ARLD + seg * 8) * 2, wl + off, true);
        }
        CP_COMMIT();
    };

    float acc[4][NTW][4];
    #pragma unroll
    for (int mt = 0; mt < 4; mt++)
        #pragma unroll
        for (int nt = 0; nt < NTW; nt++)
            #pragma unroll
            for (int e = 0; e < 4; e++) acc[mt][nt][e] = 0.f;

    load_stage(0, 0);

    for (int ci = 0; ci < NC; ci++) {
        if (ci + 1 < NC) { load_stage(ci + 1, (ci + 1) & 1); CP_WAIT(1); }
        else             { CP_WAIT(0); }
        __syncthreads();

        __half* st = sm + (ci & 1) * STG;
        uint32_t uAh = smem_u32(st);
        uint32_t uAl = uAh + A_HALF * 2;
        uint32_t uWh = uAl + A_HALF * 2;
        uint32_t uWl = uWh + W_HALF * 2;

        #pragma unroll
        for (int ks = 0; ks < 2; ks++) {
            int acol = ks * 16 + (lane >> 4) * 8;
            unsigned ah[4][4], al[4][4];
            #pragma unroll
            for (int mt = 0; mt < 4; mt++) {
                int arow = wm * 64 + mt * 16 + (lane & 15);
                uint32_t ad = (arow * ARLD + acol) * 2;
                LDSM4(ah[mt], uAh + ad);
                LDSM4(al[mt], uAl + ad);
            }
            int bcol = ks * 16 + ((lane >> 3) & 1) * 8;
            #pragma unroll
            for (int pp = 0; pp < NPAIR; pp++) {
                int brow = wn * (NT / 4) + pp * 16 + (lane & 7) + ((lane >> 4) & 1) * 8;
                uint32_t bd = (brow * ARLD + bcol) * 2;
                unsigned bh[4], bl[4];
                LDSM4(bh, uWh + bd);
                LDSM4(bl, uWl + bd);
                #pragma unroll
                for (int mt = 0; mt < 4; mt++) {
                    mma_fp16(acc[mt][2 * pp + 0], ah[mt], bh);
                    mma_fp16(acc[mt][2 * pp + 0], al[mt], bh);
                    mma_fp16(acc[mt][2 * pp + 0], ah[mt], bl);
                    mma_fp16(acc[mt][2 * pp + 1], ah[mt], bh + 2);
                    mma_fp16(acc[mt][2 * pp + 1], al[mt], bh + 2);
                    mma_fp16(acc[mt][2 * pp + 1], ah[mt], bl + 2);
                }
            }
        }
        __syncthreads();
    }

    // ---------------- epilogue ----------------
    int r    = lane >> 2;
    int tid4 = lane & 3;
    #pragma unroll
    for (int nt = 0; nt < NTW; nt++) {
        int oc0 = o0 + wn * (NT / 4) + nt * 8 + tid4 * 2;
        float b0 = __ldg(&bias[oc0]);
        float b1 = __ldg(&bias[oc0 + 1]);
        #pragma unroll
        for (int mt = 0; mt < 4; mt++) {
            #pragma unroll
            for (int half = 0; half < 2; half++) {
                int px = p0 + wm * 64 + mt * 16 + r + half * 8;
                float v0 = acc[mt][nt][half * 2 + 0] + b0;
                float v1 = acc[mt][nt][half * 2 + 1] + b1;
                if (MODE == 0) {
                    v0 = gelu_exact(v0);
                    v1 = gelu_exact(v1);
                    __half h0 = __float2half(v0), h1 = __float2half(v1);
                    __half l0 = __float2half(v0 - __half2float(h0));
                    __half l1 = __float2half(v1 - __half2float(h1));
                    size_t a = (size_t)px * COUT + oc0;
                    *reinterpret_cast<__half2*>(&outh[a]) = __halves2half2(h0, h1);
                    *reinterpret_cast<__half2*>(&outl[a]) = __halves2half2(l0, l1);
                } else {
                    int b  = px / HWP;
                    int hw = px - b * HWP;
                    size_t a0 = ((size_t)b * COUT + oc0) * HWP + hw;
                    size_t a1 = a0 + HWP;
                    outf[a0] = v0 + res[a0];
                    outf[a1] = v1 + res[a1];
                }
            }
        }
    }
}

// ---------------- launcher -----------------------------------------------------
extern "C" void kernel_launch(void* const* d_in, const int* in_sizes, int n_in,
                              void* d_out, int out_size) {
    const float* x       = (const float*)d_in[0];
    const float* ln1_g   = (const float*)d_in[1];
    const float* ln1_b   = (const float*)d_in[2];
    const float* qkv_w   = (const float*)d_in[3];
    const float* qkv_b   = (const float*)d_in[4];
    const float* proj_w  = (const float*)d_in[5];
    const float* proj_b  = (const float*)d_in[6];
    const float* ln2_g   = (const float*)d_in[7];
    const float* ln2_b   = (const float*)d_in[8];
    const float* conv1_w = (const float*)d_in[9];
    const float* conv1_b = (const float*)d_in[10];
    const float* conv2_w = (const float*)d_in[11];
    const float* conv2_b = (const float*)d_in[12];
    float* out = (float*)d_out;

    float* xw  = nullptr; cudaGetSymbolAddress((void**)&xw,  g_xw);
    float* qkv = nullptr; cudaGetSymbolAddress((void**)&qkv, g_qkv);
    float* att = nullptr; cudaGetSymbolAddress((void**)&att, g_attn);
    float* x1  = nullptr; cudaGetSymbolAddress((void**)&x1,  g_x1);
    __half *ah, *al, *hh, *hl, *w1h, *w1l, *w2h, *w2l;
    cudaGetSymbolAddress((void**)&ah,  g_ah);
    cudaGetSymbolAddress((void**)&al,  g_al);
    cudaGetSymbolAddress((void**)&hh,  g_hh);
    cudaGetSymbolAddress((void**)&hl,  g_hl);
    cudaGetSymbolAddress((void**)&w1h, g_w1h);
    cudaGetSymbolAddress((void**)&w1l, g_w1l);
    cudaGetSymbolAddress((void**)&w2h, g_w2h);
    cudaGetSymbolAddress((void**)&w2l, g_w2l);

    const int NW = 1327104;
    split_w<<<(NW + 255) / 256, 256>>>(conv1_w, w1h, w1l, 768, 192);
    split_w<<<(NW + 255) / 256, 256>>>(conv2_w, w2h, w2l, 192, 768);

    ln1_roll_window<<<NROWS / 256, 256>>>(x, ln1_g, ln1_b, xw);
    gemm_nt<<<dim3(NROWS / 128, 576 / 64), 256>>>(xw, qkv_w, qkv_b, qkv, NROWS, 576, 192);
    attn_kernel<<<NWIN * HEADS, 64>>>(qkv, att);
    gemm_nt<<<dim3(NROWS / 128, 192 / 64), 256>>>(att, proj_w, proj_b, xw, NROWS, 192, 192);
    unwindow_residual<<<(BB * CC * HWP) / 256, 256>>>(x, xw, x1);
    ln2_nhwc<<<NROWS / 256, 256>>>(x1, ln2_g, ln2_b, ah, al);

    // conv1: 192->768, NT=256 (3 oc tiles). smem halves per stage: 2*128*40 + 2*256*40
    const int SM1 = (2 * 128 * 40 + 2 * 256 * 40) * 2 * 2;   // bytes, 2 stages
    cudaFuncSetAttribute(conv3x3_hmma<192, 768, 256, 0>,
                         cudaFuncAttributeMaxDynamicSharedMemorySize, SM1);
    conv3x3_hmma<192, 768, 256, 0><<<dim3(784, 3), 256, SM1>>>(
        ah, al, w1h, w1l, conv1_b, nullptr, nullptr, hh, hl);

    // conv2: 768->192, NT=192 (1 oc tile)
    const int SM2 = (2 * 128 * 40 + 2 * 192 * 40) * 2 * 2;
    cudaFuncSetAttribute(conv3x3_hmma<768, 192, 192, 1>,
                         cudaFuncAttributeMaxDynamicSharedMemorySize, SM2);
    conv3x3_hmma<768, 192, 192, 1><<<dim3(784, 1), 256, SM2>>>(
        hh, hl, w2h, w2l, conv2_b, x1, out, nullptr, nullptr);
}

// round 8
// speedup vs baseline: 2.8282x; 1.1071x over previous
#include <cuda_runtime.h>
#include <cuda_fp16.h>
#include <math.h>
#include <stdint.h>

// ---------------- problem constants ----------------
#define BB 32
#define CC 192
#define HH 56
#define WW 56
#define HWP 3136            // 56*56
#define HEADS 6
#define DH 32
#define WSZ 7
#define NWH 8
#define NWIN 2048
#define NTOK 49
#define NROWS 100352        // 32*3136
#define HID 768
#define EPS_LN 1e-5f

// ---------------- scratch (static device globals) -----------------------------
__device__ __align__(128) float g_qkv [100352 * 576];
__device__ __align__(128) float g_proj[100352 * 192];
__device__ __align__(128) float g_x1  [19267584];
// fp16 hi/lo activation buffers
__device__ __align__(128) __half g_xwh[100352 * 192], g_xwl[100352 * 192];  // ln1+window
__device__ __align__(128) __half g_ath[100352 * 192], g_atl[100352 * 192];  // attn out
__device__ __align__(128) __half g_ah [100352 * 192], g_al [100352 * 192];  // ln2 out (NHWC)
__device__ __align__(128) __half g_hh [100352 * 768], g_hl [100352 * 768];  // conv1 out (NHWC)
// split fp16 weights
__device__ __align__(128) __half g_w1h[1327104], g_w1l[1327104];            // tap-major conv
__device__ __align__(128) __half g_w2h[1327104], g_w2l[1327104];
__device__ __align__(128) __half g_qwh[110592],  g_qwl[110592];             // [576][192]
__device__ __align__(128) __half g_pwh[36864],   g_pwl[36864];              // [192][192]

// ---------------- helpers ------------------------------------------------------
__device__ __forceinline__ uint32_t smem_u32(const void* p) {
    uint32_t a;
    asm("{ .reg .u64 t; cvta.to.shared.u64 t, %1; cvt.u32.u64 %0, t; }" : "=r"(a) : "l"(p));
    return a;
}
__device__ __forceinline__ void cp16(uint32_t dst, const void* src, bool pred) {
    int sz = pred ? 16 : 0;
    asm volatile("cp.async.cg.shared.global [%0], [%1], 16, %2;"
                 :: "r"(dst), "l"(src), "r"(sz) : "memory");
}
#define CP_COMMIT() asm volatile("cp.async.commit_group;" ::: "memory")
#define CP_WAIT(N)  asm volatile("cp.async.wait_group %0;" :: "n"(N) : "memory")
#define LDSM4(r, a)                                                              \
    asm volatile("ldmatrix.sync.aligned.m8n8.x4.shared.b16 {%0,%1,%2,%3}, [%4];" \
                 : "=r"((r)[0]), "=r"((r)[1]), "=r"((r)[2]), "=r"((r)[3]) : "r"(a))

__device__ __forceinline__ void mma_fp16(float* c, const unsigned* a, const unsigned* b) {
    asm volatile(
        "mma.sync.aligned.m16n8k16.row.col.f32.f16.f16.f32 "
        "{%0,%1,%2,%3}, {%4,%5,%6,%7}, {%8,%9}, {%0,%1,%2,%3};\n"
        : "+f"(c[0]), "+f"(c[1]), "+f"(c[2]), "+f"(c[3])
        : "r"(a[0]), "r"(a[1]), "r"(a[2]), "r"(a[3]), "r"(b[0]), "r"(b[1]));
}
__device__ __forceinline__ float gelu_exact(float v) {
    return 0.5f * v * (1.f + erff(v * 0.70710678118654752f));
}

// ---------------- weight splits -------------------------------------------------
// conv: [O][I][3][3] fp32 -> [O][tap][I] fp16 hi/lo
__global__ __launch_bounds__(256)
void split_w(const float* __restrict__ w, __half* __restrict__ hi,
             __half* __restrict__ lo, int O, int I) {
    int idx = blockIdx.x * 256 + threadIdx.x;
    int n = O * I * 9;
    if (idx >= n) return;
    int o = idx / (I * 9);
    int rem = idx - o * (I * 9);
    int i = rem / 9;
    int tap = rem - i * 9;
    float v = w[idx];
    __half h = __float2half(v);
    int dst = o * (9 * I) + tap * I + i;
    hi[dst] = h;
    lo[dst] = __float2half(v - __half2float(h));
}
// plain elementwise split (gemm weights)
__global__ __launch_bounds__(256)
void split_gw(const float* __restrict__ w, __half* __restrict__ hi,
              __half* __restrict__ lo, int n) {
    int i = blockIdx.x * 256 + threadIdx.x;
    if (i >= n) return;
    float v = w[i];
    __half h = __float2half(v);
    hi[i] = h;
    lo[i] = __float2half(v - __half2float(h));
}

// ---------------- LN1 + roll(-3,-3) + window partition -> fp16 hi/lo -----------
__global__ __launch_bounds__(256)
void ln1_roll_window(const float* __restrict__ x, const float* __restrict__ g,
                     const float* __restrict__ bt, __half* __restrict__ oh,
                     __half* __restrict__ ol) {
    int idx = blockIdx.x * 256 + threadIdx.x;
    if (idx >= NROWS) return;
    int bb = idx / HWP;
    int hw = idx - bb * HWP;
    int h1 = hw / WW;
    int w1 = hw - h1 * WW;
    int hs = h1 + 3; if (hs >= HH) hs -= HH;
    int ws = w1 + 3; if (ws >= WW) ws -= WW;
    const float* xp = x + (size_t)bb * CC * HWP + hs * WW + ws;
    float s = 0.f, ss = 0.f;
    #pragma unroll 4
    for (int c = 0; c < CC; c++) { float v = xp[(size_t)c * HWP]; s += v; ss += v * v; }
    float mean = s * (1.f / CC);
    float var  = ss * (1.f / CC) - mean * mean;
    float rstd = rsqrtf(var + EPS_LN);
    int win = bb * 64 + (h1 / WSZ) * NWH + (w1 / WSZ);
    int t   = (h1 % WSZ) * WSZ + (w1 % WSZ);
    size_t ro = ((size_t)win * NTOK + t) * CC;
    #pragma unroll 4
    for (int c = 0; c < CC; c++) {
        float v = (xp[(size_t)c * HWP] - mean) * rstd * g[c] + bt[c];
        __half h = __float2half(v);
        oh[ro + c] = h;
        ol[ro + c] = __float2half(v - __half2float(h));
    }
}

// ---------------- LN2: NCHW fp32 -> NHWC fp16 hi/lo ----------------------------
__global__ __launch_bounds__(256)
void ln2_nhwc(const float* __restrict__ x, const float* __restrict__ g,
              const float* __restrict__ bt, __half* __restrict__ oh,
              __half* __restrict__ ol) {
    int idx = blockIdx.x * 256 + threadIdx.x;
    if (idx >= NROWS) return;
    int bb = idx / HWP;
    int hw = idx - bb * HWP;
    const float* xp = x + (size_t)bb * CC * HWP + hw;
    float s = 0.f, ss = 0.f;
    #pragma unroll 4
    for (int c = 0; c < CC; c++) { float v = xp[(size_t)c * HWP]; s += v; ss += v * v; }
    float mean = s * (1.f / CC);
    float var  = ss * (1.f / CC) - mean * mean;
    float rstd = rsqrtf(var + EPS_LN);
    __half* ph = oh + (size_t)idx * CC;
    __half* pl = ol + (size_t)idx * CC;
    #pragma unroll 4
    for (int c = 0; c < CC; c++) {
        float v = (xp[(size_t)c * HWP] - mean) * rstd * g[c] + bt[c];
        __half h = __float2half(v);
        ph[c] = h;
        pl[c] = __float2half(v - __half2float(h));
    }
}

// ---------------- fp16-split HMMA GEMM: C[M,Ntot] = A[M,K]*B[n,K]^T + bias -----
// Block: 128 m x NT n. 8 warps (2m x 4n). K chunks of 32. 3-term split.
template<int KK, int NT>
__global__ __launch_bounds__(256, 1)
void gemm_hmma(const __half* __restrict__ xh, const __half* __restrict__ xl,
               const __half* __restrict__ wh, const __half* __restrict__ wl,
               const float* __restrict__ bias, float* __restrict__ out, int Ntot) {
    constexpr int NC     = KK / 32;
    constexpr int NTW    = NT / 4 / 8;
    constexpr int NPAIR  = NTW / 2;
    constexpr int ARLD   = 40;
    constexpr int A_HALF = 128 * ARLD;
    constexpr int W_HALF = NT * ARLD;
    constexpr int STG    = 2 * A_HALF + 2 * W_HALF;

    extern __shared__ __half sm[];
    int tid  = threadIdx.x;
    int lane = tid & 31;
    int wid  = tid >> 5;
    int wm = wid & 1, wn = wid >> 1;
    int p0 = blockIdx.x * 128, o0 = blockIdx.y * NT;
    int ar0 = tid >> 2, seg = tid & 3;

    auto load_stage = [&](int ci, int s) {
        uint32_t uAh = smem_u32(sm + s * STG);
        uint32_t uAl = uAh + A_HALF * 2;
        uint32_t uWh = uAl + A_HALF * 2;
        uint32_t uWl = uWh + W_HALF * 2;
        int kt = ci * 32;
        #pragma unroll
        for (int q = 0; q < 2; q++) {
            int row = ar0 + q * 64;
            size_t off = (size_t)(p0 + row) * KK + kt + seg * 8;
            cp16(uAh + (row * ARLD + seg * 8) * 2, xh + off, true);
            cp16(uAl + (row * ARLD + seg * 8) * 2, xl + off, true);
        }
        #pragma unroll
        for (int j = 0; j < (NT + 63) / 64; j++) {
            int row = j * 64 + ar0;
            if (NT % 64 == 0 || row < NT) {
                size_t off = (size_t)(o0 + row) * KK + kt + seg * 8;
                cp16(uWh + (row * ARLD + seg * 8) * 2, wh + off, true);
                cp16(uWl + (row * ARLD + seg * 8) * 2, wl + off, true);
            }
        }
        CP_COMMIT();
    };

    float acc[4][NTW][4];
    #pragma unroll
    for (int mt = 0; mt < 4; mt++)
        #pragma unroll
        for (int nt = 0; nt < NTW; nt++)
            #pragma unroll
            for (int e = 0; e < 4; e++) acc[mt][nt][e] = 0.f;

    load_stage(0, 0);
    for (int ci = 0; ci < NC; ci++) {
        if (ci + 1 < NC) { load_stage(ci + 1, (ci + 1) & 1); CP_WAIT(1); }
        else             { CP_WAIT(0); }
        __syncthreads();
        uint32_t uAh = smem_u32(sm + (ci & 1) * STG);
        uint32_t uAl = uAh + A_HALF * 2;
        uint32_t uWh = uAl + A_HALF * 2;
        uint32_t uWl = uWh + W_HALF * 2;
        #pragma unroll
        for (int ks = 0; ks < 2; ks++) {
            int acol = ks * 16 + (lane >> 4) * 8;
            unsigned ah[4][4], al[4][4];
            #pragma unroll
            for (int mt = 0; mt < 4; mt++) {
                uint32_t ad = ((wm * 64 + mt * 16 + (lane & 15)) * ARLD + acol) * 2;
                LDSM4(ah[mt], uAh + ad);
                LDSM4(al[mt], uAl + ad);
            }
            int bcol = ks * 16 + ((lane >> 3) & 1) * 8;
            #pragma unroll
            for (int pp = 0; pp < NPAIR; pp++) {
                int brow = wn * (NT / 4) + pp * 16 + (lane & 7) + ((lane >> 4) & 1) * 8;
                uint32_t bd = (brow * ARLD + bcol) * 2;
                unsigned bh[4], bl[4];
                LDSM4(bh, uWh + bd);
                LDSM4(bl, uWl + bd);
                #pragma unroll
                for (int mt = 0; mt < 4; mt++) {
                    mma_fp16(acc[mt][2 * pp + 0], ah[mt], bh);
                    mma_fp16(acc[mt][2 * pp + 0], al[mt], bh);
                    mma_fp16(acc[mt][2 * pp + 0], ah[mt], bl);
                    mma_fp16(acc[mt][2 * pp + 1], ah[mt], bh + 2);
                    mma_fp16(acc[mt][2 * pp + 1], al[mt], bh + 2);
                    mma_fp16(acc[mt][2 * pp + 1], ah[mt], bl + 2);
                }
            }
        }
        __syncthreads();
    }
    int r = lane >> 2, tid4 = lane & 3;
    #pragma unroll
    for (int nt = 0; nt < NTW; nt++) {
        int oc0 = o0 + wn * (NT / 4) + nt * 8 + tid4 * 2;
        float b0 = __ldg(&bias[oc0]);
        float b1 = __ldg(&bias[oc0 + 1]);
        #pragma unroll
        for (int mt = 0; mt < 4; mt++) {
            #pragma unroll
            for (int half = 0; half < 2; half++) {
                int px = p0 + wm * 64 + mt * 16 + r + half * 8;
                float2 v;
                v.x = acc[mt][nt][half * 2 + 0] + b0;
                v.y = acc[mt][nt][half * 2 + 1] + b1;
                *reinterpret_cast<float2*>(&out[(size_t)px * Ntot + oc0]) = v;
            }
        }
    }
}

// ---------------- windowed attention (fp32 in, fp16 hi/lo out) -----------------
__global__ __launch_bounds__(64)
void attn_kernel(const float* __restrict__ qkv, __half* __restrict__ oh,
                 __half* __restrict__ ol) {
    __shared__ float qs[NTOK * 33];
    __shared__ float ks[NTOK * 33];
    __shared__ float vs[NTOK * 33];
    __shared__ float sc[NTOK * 51];
    int win  = blockIdx.x / HEADS;
    int head = blockIdx.x - win * HEADS;
    int tid = threadIdx.x;
    for (int i = tid; i < NTOK * DH; i += 64) {
        int t = i >> 5;
        int d = i & 31;
        size_t rb = ((size_t)win * NTOK + t) * 576 + head * DH + d;
        qs[t * 33 + d] = qkv[rb];
        ks[t * 33 + d] = qkv[rb + 192];
        vs[t * 33 + d] = qkv[rb + 384];
    }
    __syncthreads();
    int i = tid;
    if (i < NTOK) {
        const float scale = 0.17677669529663687f;
        float mx = -1e30f;
        for (int j = 0; j < NTOK; j++) {
            float dot = 0.f;
            #pragma unroll
            for (int d = 0; d < DH; d++) dot += qs[i * 33 + d] * ks[j * 33 + d];
            dot *= scale;
            sc[i * 51 + j] = dot;
            mx = fmaxf(mx, dot);
        }
        float sum = 0.f;
        for (int j = 0; j < NTOK; j++) {
            float e = expf(sc[i * 51 + j] - mx);
            sc[i * 51 + j] = e;
            sum += e;
        }
        float inv = 1.f / sum;
        size_t ro = ((size_t)win * NTOK + i) * CC + head * DH;
        #pragma unroll
        for (int d = 0; d < DH; d++) {
            float o = 0.f;
            for (int j = 0; j < NTOK; j++) o += sc[i * 51 + j] * vs[j * 33 + d];
            o *= inv;
            __half h = __float2half(o);
            oh[ro + d] = h;
            ol[ro + d] = __float2half(o - __half2float(h));
        }
    }
}

// ---------------- un-window + roll + residual ----------------------------------
__global__ __launch_bounds__(256)
void unwindow_residual(const float* __restrict__ x, const float* __restrict__ proj,
                       float* __restrict__ x1) {
    int idx = blockIdx.x * 256 + threadIdx.x;
    if (idx >= BB * CC * HWP) return;
    int b = idx / (CC * HWP);
    int r = idx - b * (CC * HWP);
    int c = r / HWP;
    int hw = r - c * HWP;
    int h = hw / WW;
    int w = hw - h * WW;
    int hr = h - 3; if (hr < 0) hr += HH;
    int wr = w - 3; if (wr < 0) wr += WW;
    int row = (b * 64 + (hr / WSZ) * NWH + (wr / WSZ)) * NTOK + (hr % WSZ) * WSZ + (wr % WSZ);
    x1[idx] = x[idx] + proj[(size_t)row * CC + c];
}

// ---------------- fp16 HMMA implicit-GEMM 3x3 conv -----------------------------
// Block: 128 px x NT oc. 8 warps (2m x 4n). K chunks of 32 (tap-major).
// TERMS=3: Xh*Wh + Xl*Wh + Xh*Wl.  TERMS=2: Xh*Wh + Xl*Wh (weight hi only).
// MODE 0: bias+GELU -> NHWC fp16 hi/lo. MODE 1: bias+residual -> NCHW fp32.
template<int CIN, int COUT, int NT, int MODE, int TERMS>
__global__ __launch_bounds__(256, 1)
void conv3x3_hmma(const __half* __restrict__ xh, const __half* __restrict__ xl,
                  const __half* __restrict__ wh, const __half* __restrict__ wl,
                  const float* __restrict__ bias, const float* __restrict__ res,
                  float* __restrict__ outf, __half* __restrict__ outh,
                  __half* __restrict__ outl) {
    constexpr int K      = CIN * 9;
    constexpr int NC     = K / 32;
    constexpr int CPT    = CIN / 32;
    constexpr int NTW    = NT / 4 / 8;
    constexpr int NPAIR  = NTW / 2;
    constexpr int ARLD   = 40;
    constexpr int A_HALF = 128 * ARLD;
    constexpr int W_HALF = NT * ARLD;
    constexpr int STG    = 2 * A_HALF + 2 * W_HALF;

    extern __shared__ __half sm[];
    int tid  = threadIdx.x;
    int lane = tid & 31;
    int wid  = tid >> 5;
    int wm = wid & 1, wn = wid >> 1;
    int p0 = blockIdx.x * 128, o0 = blockIdx.y * NT;

    int ar0 = tid >> 2, seg = tid & 3;
    int bA[2], hA[2], wA[2];
    #pragma unroll
    for (int q = 0; q < 2; q++) {
        int px = p0 + ar0 + q * 64;
        int b  = px / HWP;
        int hw = px - b * HWP;
        bA[q] = b; hA[q] = hw / WW; wA[q] = hw - (hw / WW) * WW;
    }

    auto load_stage = [&](int ci, int s) {
        uint32_t uAh = smem_u32(sm + s * STG);
        uint32_t uAl = uAh + A_HALF * 2;
        uint32_t uWh = uAl + A_HALF * 2;
        uint32_t uWl = uWh + W_HALF * 2;
        int tap = ci / CPT;
        int c0  = (ci - tap * CPT) * 32;
        int kh = tap / 3 - 1, kw = tap - (tap / 3) * 3 - 1;
        int kt = ci * 32;
        #pragma unroll
        for (int q = 0; q < 2; q++) {
            int row = ar0 + q * 64;
            int h2 = hA[q] + kh, w2 = wA[q] + kw;
            bool ok = ((unsigned)h2 < (unsigned)HH) && ((unsigned)w2 < (unsigned)WW);
            size_t off = ((size_t)(bA[q] * HWP + h2 * WW + w2)) * CIN + c0 + seg * 8;
            cp16(uAh + (row * ARLD + seg * 8) * 2, ok ? xh + off : xh, ok);
            cp16(uAl + (row * ARLD + seg * 8) * 2, ok ? xl + off : xl, ok);
        }
        #pragma unroll
        for (int j = 0; j < NT / 64; j++) {
            int row = j * 64 + ar0;
            size_t off = (size_t)(o0 + row) * K + kt + seg * 8;
            cp16(uWh + (row * ARLD + seg * 8) * 2, wh + off, true);
            if (TERMS == 3)
                cp16(uWl + (row * ARLD + seg * 8) * 2, wl + off, true);
        }
        CP_COMMIT();
    };

    float acc[4][NTW][4];
    #pragma unroll
    for (int mt = 0; mt < 4; mt++)
        #pragma unroll
        for (int nt = 0; nt < NTW; nt++)
            #pragma unroll
            for (int e = 0; e < 4; e++) acc[mt][nt][e] = 0.f;

    load_stage(0, 0);
    for (int ci = 0; ci < NC; ci++) {
        if (ci + 1 < NC) { load_stage(ci + 1, (ci + 1) & 1); CP_WAIT(1); }
        else             { CP_WAIT(0); }
        __syncthreads();
        uint32_t uAh = smem_u32(sm + (ci & 1) * STG);
        uint32_t uAl = uAh + A_HALF * 2;
        uint32_t uWh = uAl + A_HALF * 2;
        uint32_t uWl = uWh + W_HALF * 2;
        #pragma unroll
        for (int ks = 0; ks < 2; ks++) {
            int acol = ks * 16 + (lane >> 4) * 8;
            unsigned ah[4][4], al[4][4];
            #pragma unroll
            for (int mt = 0; mt < 4; mt++) {
                uint32_t ad = ((wm * 64 + mt * 16 + (lane & 15)) * ARLD + acol) * 2;
                LDSM4(ah[mt], uAh + ad);
                LDSM4(al[mt], uAl + ad);
            }
            int bcol = ks * 16 + ((lane >> 3) & 1) * 8;
            #pragma unroll
            for (int pp = 0; pp < NPAIR; pp++) {
                int brow = wn * (NT / 4) + pp * 16 + (lane & 7) + ((lane >> 4) & 1) * 8;
                uint32_t bd = (brow * ARLD + bcol) * 2;
                unsigned bh[4], bl[4];
                LDSM4(bh, uWh + bd);
                if (TERMS == 3) LDSM4(bl, uWl + bd);
                #pragma unroll
                for (int mt = 0; mt < 4; mt++) {
                    mma_fp16(acc[mt][2 * pp + 0], ah[mt], bh);
                    mma_fp16(acc[mt][2 * pp + 0], al[mt], bh);
                    if (TERMS == 3) mma_fp16(acc[mt][2 * pp + 0], ah[mt], bl);
                    mma_fp16(acc[mt][2 * pp + 1], ah[mt], bh + 2);
                    mma_fp16(acc[mt][2 * pp + 1], al[mt], bh + 2);
                    if (TERMS == 3) mma_fp16(acc[mt][2 * pp + 1], ah[mt], bl + 2);
                }
            }
        }
        __syncthreads();
    }

    int r = lane >> 2, tid4 = lane & 3;
    #pragma unroll
    for (int nt = 0; nt < NTW; nt++) {
        int oc0 = o0 + wn * (NT / 4) + nt * 8 + tid4 * 2;
        float b0 = __ldg(&bias[oc0]);
        float b1 = __ldg(&bias[oc0 + 1]);
        #pragma unroll
        for (int mt = 0; mt < 4; mt++) {
            #pragma unroll
            for (int half = 0; half < 2; half++) {
                int px = p0 + wm * 64 + mt * 16 + r + half * 8;
                float v0 = acc[mt][nt][half * 2 + 0] + b0;
                float v1 = acc[mt][nt][half * 2 + 1] + b1;
                if (MODE == 0) {
                    v0 = gelu_exact(v0);
                    v1 = gelu_exact(v1);
                    __half h0 = __float2half(v0), h1 = __float2half(v1);
                    __half l0 = __float2half(v0 - __half2float(h0));
                    __half l1 = __float2half(v1 - __half2float(h1));
                    size_t a = (size_t)px * COUT + oc0;
                    *reinterpret_cast<__half2*>(&outh[a]) = __halves2half2(h0, h1);
                    *reinterpret_cast<__half2*>(&outl[a]) = __halves2half2(l0, l1);
                } else {
                    int b  = px / HWP;
                    int hw = px - b * HWP;
                    size_t a0 = ((size_t)b * COUT + oc0) * HWP + hw;
                    size_t a1 = a0 + HWP;
                    outf[a0] = v0 + res[a0];
                    outf[a1] = v1 + res[a1];
                }
            }
        }
    }
}

// ---------------- launcher -----------------------------------------------------
extern "C" void kernel_launch(void* const* d_in, const int* in_sizes, int n_in,
                              void* d_out, int out_size) {
    const float* x       = (const float*)d_in[0];
    const float* ln1_g   = (const float*)d_in[1];
    const float* ln1_b   = (const float*)d_in[2];
    const float* qkv_w   = (const float*)d_in[3];
    const float* qkv_b   = (const float*)d_in[4];
    const float* proj_w  = (const float*)d_in[5];
    const float* proj_b  = (const float*)d_in[6];
    const float* ln2_g   = (const float*)d_in[7];
    const float* ln2_b   = (const float*)d_in[8];
    const float* conv1_w = (const float*)d_in[9];
    const float* conv1_b = (const float*)d_in[10];
    const float* conv2_w = (const float*)d_in[11];
    const float* conv2_b = (const float*)d_in[12];
    float* out = (float*)d_out;

    float* qkv = nullptr; cudaGetSymbolAddress((void**)&qkv, g_qkv);
    float* prj = nullptr; cudaGetSymbolAddress((void**)&prj, g_proj);
    float* x1  = nullptr; cudaGetSymbolAddress((void**)&x1,  g_x1);
    __half *xwh, *xwl, *ath, *atl, *ah, *al, *hh, *hl;
    __half *w1h, *w1l, *w2h, *w2l, *qwh, *qwl, *pwh, *pwl;
    cudaGetSymbolAddress((void**)&xwh, g_xwh);
    cudaGetSymbolAddress((void**)&xwl, g_xwl);
    cudaGetSymbolAddress((void**)&ath, g_ath);
    cudaGetSymbolAddress((void**)&atl, g_atl);
    cudaGetSymbolAddress((void**)&ah,  g_ah);
    cudaGetSymbolAddress((void**)&al,  g_al);
    cudaGetSymbolAddress((void**)&hh,  g_hh);
    cudaGetSymbolAddress((void**)&hl,  g_hl);
    cudaGetSymbolAddress((void**)&w1h, g_w1h);
    cudaGetSymbolAddress((void**)&w1l, g_w1l);
    cudaGetSymbolAddress((void**)&w2h, g_w2h);
    cudaGetSymbolAddress((void**)&w2l, g_w2l);
    cudaGetSymbolAddress((void**)&qwh, g_qwh);
    cudaGetSymbolAddress((void**)&qwl, g_qwl);
    cudaGetSymbolAddress((void**)&pwh, g_pwh);
    cudaGetSymbolAddress((void**)&pwl, g_pwl);

    const int NW = 1327104;
    split_w<<<(NW + 255) / 256, 256>>>(conv1_w, w1h, w1l, 768, 192);
    split_w<<<(NW + 255) / 256, 256>>>(conv2_w, w2h, w2l, 192, 768);
    split_gw<<<(110592 + 255) / 256, 256>>>(qkv_w, qwh, qwl, 110592);
    split_gw<<<(36864 + 255) / 256, 256>>>(proj_w, pwh, pwl, 36864);

    ln1_roll_window<<<NROWS / 256, 256>>>(x, ln1_g, ln1_b, xwh, xwl);

    // qkv GEMM: [100352,192] x [576,192]^T  (HMMA, 3-term)
    const int SMG = (2 * 128 * 40 + 2 * 64 * 40) * 2 * 2;
    cudaFuncSetAttribute(gemm_hmma<192, 64>,
                         cudaFuncAttributeMaxDynamicSharedMemorySize, SMG);
    gemm_hmma<192, 64><<<dim3(784, 9), 256, SMG>>>(xwh, xwl, qwh, qwl, qkv_b, qkv, 576);

    attn_kernel<<<NWIN * HEADS, 64>>>(qkv, ath, atl);

    gemm_hmma<192, 64><<<dim3(784, 3), 256, SMG>>>(ath, atl, pwh, pwl, proj_b, prj, 192);

    unwindow_residual<<<(BB * CC * HWP) / 256, 256>>>(x, prj, x1);
    ln2_nhwc<<<NROWS / 256, 256>>>(x1, ln2_g, ln2_b, ah, al);

    // conv1: 192->768, NT=256, 2-term (weight-hi only)
    const int SM1 = (2 * 128 * 40 + 2 * 256 * 40) * 2 * 2;
    cudaFuncSetAttribute(conv3x3_hmma<192, 768, 256, 0, 2>,
                         cudaFuncAttributeMaxDynamicSharedMemorySize, SM1);
    conv3x3_hmma<192, 768, 256, 0, 2><<<dim3(784, 3), 256, SM1>>>(
        ah, al, w1h, w1l, conv1_b, nullptr, nullptr, hh, hl);

    // conv2: 768->192, NT=192, 3-term
    const int SM2 = (2 * 128 * 40 + 2 * 192 * 40) * 2 * 2;
    cudaFuncSetAttribute(conv3x3_hmma<768, 192, 192, 1, 3>,
                         cudaFuncAttributeMaxDynamicSharedMemorySize, SM2);
    conv3x3_hmma<768, 192, 192, 1, 3><<<dim3(784, 1), 256, SM2>>>(
        hh, hl, w2h, w2l, conv2_b, x1, out, nullptr, nullptr);
}